// round 14
// baseline (speedup 1.0000x reference)
#include <cuda_runtime.h>
#include <cuda_bf16.h>
#include <math.h>
#include <stdint.h>

// ---------------- problem constants ----------------
#define NN    20000     // nodes
#define EE    5000      // hyperedges
#define NNZV  200000    // incidences
#define DH    6         // sheaf dim d
#define HID   9         // MLP hidden
#define FIN   256       // input features
#define OUTD  4968      // output dim
#define PROJ  54        // DH*HID
#define ROW12 12        // padded row stride (floats) for 9-wide rows
#define NLAY  2

// packed split-bf16 GEMM operand layout: [hi(54) | lo(54) | hi(54)] -> 162, pad to 176
#define KPACK   162
#define KTOT    176                  // 11 k16 steps, chunks [64|64|48]
#define A_ROWS_PAD 20096             // 157*128
#define B_ROWS_PAD 5120              // 20*256

// ---------------- scratch (static device globals; no runtime alloc) ----------------
// Device globals are zero-initialized at module load; padding regions of
// g_Abf/g_Bbf (cols 162..175, rows >= NN/OUTD) are never written -> stay zero.
__device__ __align__(16) float g_xm[NN * ROW12];
__device__ __align__(16) float g_em[EE * ROW12];
__device__ __align__(16) float g_hsheaf[(size_t)NNZV * DH];
__device__ int   g_cnt_node[NN];
__device__ int   g_cnt_edge[EE];
__device__ int   g_noff[NN + 1];
__device__ int   g_eoff[EE + 1];
__device__ int   g_ncur[NN];
__device__ int   g_ecur[EE];
__device__ int   g_bsum_e[32];
__device__ int   g_bsum_n[32];
__device__ __align__(8) int2 g_elist[NNZV];   // (k, node)
__device__ __align__(8) int2 g_nlist[NNZV];   // (k, edge)
__device__ __align__(16) float g_h0[(size_t)NN * DH * ROW12];
__device__ __align__(16) float g_m[(size_t)EE * DH * ROW12];
__device__ __align__(16) __nv_bfloat16 g_Abf[(size_t)A_ROWS_PAD * KTOT];  // 7.1 MB
__device__ __align__(16) __nv_bfloat16 g_Bbf[(size_t)B_ROWS_PAD * KTOT];  // 1.8 MB

// ---------------- zero counts + cursors ----------------
__global__ void zero_counts_kernel() {
    int i = blockIdx.x * blockDim.x + threadIdx.x;
    if (i < NN) { g_cnt_node[i] = 0; g_ncur[i] = 0; }
    if (i < EE) { g_cnt_edge[i] = 0; g_ecur[i] = 0; }
}

// ---------------- input projection + per-row mean + FUSED layer-0 h0 ----------------
// 16 rows per block, 64 threads (halves redundant W re-reads from L2 vs 8 rows)
#define PBR 16
__global__ void proj_kernel(const float* __restrict__ x,
                            const float* __restrict__ ha,
                            const float* __restrict__ W,
                            const float* __restrict__ b,
                            const float* __restrict__ lng0,   // conv LN gamma, layer 0
                            const float* __restrict__ lnb0,   // conv LN beta, layer 0
                            const float* __restrict__ cw0,    // conv W, layer 0 (9x9)
                            const float* __restrict__ cb0)    // conv b, layer 0
{
    __shared__ float sx[PBR][FIN];
    __shared__ float sout[PBR][PROJ];
    __shared__ float sW0[HID * HID], sg0[HID], sb0[HID], scb0[HID];
    int r0 = blockIdx.x * PBR;
    int t  = threadIdx.x;

    for (int i = t; i < HID * HID; i += 64) sW0[i] = cw0[i];
    if (t < HID) { sg0[t] = lng0[t]; sb0[t] = lnb0[t]; scb0[t] = cb0[t]; }

    #pragma unroll
    for (int rr = 0; rr < PBR; rr++) {
        int r = r0 + rr;
        if (r >= NN + EE) break;
        const float* src = (r < NN) ? (x + (size_t)r * FIN) : (ha + (size_t)(r - NN) * FIN);
        for (int c = t; c < FIN; c += 64) sx[rr][c] = src[c];
    }
    __syncthreads();

    if (t < PROJ) {
        float acc[PBR];
        float bt = b[t];
        #pragma unroll
        for (int rr = 0; rr < PBR; rr++) acc[rr] = bt;
        #pragma unroll 4
        for (int c = 0; c < FIN; c++) {
            float w = W[c * PROJ + t];
            #pragma unroll
            for (int rr = 0; rr < PBR; rr++) acc[rr] += w * sx[rr][c];
        }
        #pragma unroll
        for (int rr = 0; rr < PBR; rr++) {
            int r = r0 + rr;
            if (r >= NN + EE) break;
            sout[rr][t] = acc[rr];
        }
    }
    __syncthreads();

    // per-row mean over d (for sheaf builder)
    if (t < HID) {
        #pragma unroll
        for (int rr = 0; rr < PBR; rr++) {
            int r = r0 + rr;
            if (r >= NN + EE) break;
            float s = 0.f;
            #pragma unroll
            for (int j = 0; j < DH; j++) s += sout[rr][j * HID + t];
            s *= (1.0f / DH);
            if (r < NN) g_xm[(size_t)r * ROW12 + t] = s;
            else        g_em[(size_t)(r - NN) * ROW12 + t] = s;
        }
    }

    // fused layer-0 h0 (node rows only)
    if (t < PROJ) {
        int j = t / HID, c = t - (t / HID) * HID;
        #pragma unroll
        for (int rr = 0; rr < PBR; rr++) {
            int r = r0 + rr;
            if (r >= NN) break;
            float v[HID];
            #pragma unroll
            for (int h = 0; h < HID; h++) v[h] = sout[rr][j * HID + h];
            float mean = 0.f;
            #pragma unroll
            for (int h = 0; h < HID; h++) mean += v[h];
            mean *= (1.0f / HID);
            float var = 0.f;
            #pragma unroll
            for (int h = 0; h < HID; h++) { float d = v[h] - mean; var += d * d; }
            var *= (1.0f / HID);
            float rs = rsqrtf(var + 1e-5f);
            float acc = scb0[c];
            #pragma unroll
            for (int h = 0; h < HID; h++)
                acc += ((v[h] - mean) * rs * sg0[h] + sb0[h]) * sW0[h * HID + c];
            g_h0[((size_t)r * DH + j) * ROW12 + c] = acc;
        }
    }
}

// ---------------- sheaf builder (alpha + degree counts) ----------------
__global__ void sheaf_kernel(const int* __restrict__ ni, const int* __restrict__ ei,
                             const float* __restrict__ lng, const float* __restrict__ lnb,
                             const float* __restrict__ sw,  const float* __restrict__ sb)
{
    __shared__ float s_sw[2 * HID * DH];
    __shared__ float s_sb[DH];
    __shared__ float s_g[2 * HID], s_b[2 * HID];
    int t = threadIdx.x;
    if (t < 2 * HID * DH) s_sw[t] = sw[t];
    if (t < DH) s_sb[t] = sb[t];
    if (t < 2 * HID) { s_g[t] = lng[t]; s_b[t] = lnb[t]; }
    __syncthreads();

    int k = blockIdx.x * blockDim.x + threadIdx.x;
    if (k >= NNZV) return;
    int n = ni[k], e = ei[k];

    float v[2 * HID];
    {
        const float4 a0 = *(const float4*)(g_xm + (size_t)n * ROW12);
        const float4 a1 = *(const float4*)(g_xm + (size_t)n * ROW12 + 4);
        v[0]=a0.x; v[1]=a0.y; v[2]=a0.z; v[3]=a0.w;
        v[4]=a1.x; v[5]=a1.y; v[6]=a1.z; v[7]=a1.w;
        v[8] = g_xm[(size_t)n * ROW12 + 8];
        const float4 b0 = *(const float4*)(g_em + (size_t)e * ROW12);
        const float4 b1 = *(const float4*)(g_em + (size_t)e * ROW12 + 4);
        v[9]=b0.x; v[10]=b0.y; v[11]=b0.z; v[12]=b0.w;
        v[13]=b1.x; v[14]=b1.y; v[15]=b1.z; v[16]=b1.w;
        v[17] = g_em[(size_t)e * ROW12 + 8];
    }
    float mean = 0.f;
    #pragma unroll
    for (int i = 0; i < 18; i++) mean += v[i];
    mean *= (1.0f / 18.0f);
    float var = 0.f;
    #pragma unroll
    for (int i = 0; i < 18; i++) { float d = v[i] - mean; var += d * d; }
    var *= (1.0f / 18.0f);
    float rs = rsqrtf(var + 1e-5f);
    float y[18];
    #pragma unroll
    for (int i = 0; i < 18; i++) y[i] = (v[i] - mean) * rs * s_g[i] + s_b[i];

    #pragma unroll
    for (int j = 0; j < DH; j++) {
        float z = s_sb[j];
        #pragma unroll
        for (int i = 0; i < 18; i++) z += y[i] * s_sw[i * DH + j];
        float h = 1.0f / (1.0f + __expf(-z));
        g_hsheaf[(size_t)k * DH + j] = h;
    }
    atomicAdd(&g_cnt_node[n], 1);
    atomicAdd(&g_cnt_edge[e], 1);
}

// ---------------- hierarchical scan (3 stages) ----------------
__global__ void scan1_kernel()
{
    __shared__ int wsum[32];
    const int* cnt = (blockIdx.y == 0) ? g_cnt_edge : g_cnt_node;
    int* off       = (blockIdx.y == 0) ? g_eoff : g_noff;
    int* bsum      = (blockIdx.y == 0) ? g_bsum_e : g_bsum_n;
    int len        = (blockIdx.y == 0) ? EE : NN;
    int nblk       = (len + 1023) >> 10;
    if (blockIdx.x >= nblk) return;

    int t = threadIdx.x, lane = t & 31, w = t >> 5;
    int i = blockIdx.x * 1024 + t;
    int v = (i < len) ? cnt[i] : 0;

    int sv = v;
    #pragma unroll
    for (int d = 1; d < 32; d <<= 1) {
        int u = __shfl_up_sync(0xFFFFFFFF, sv, d);
        if (lane >= d) sv += u;
    }
    if (lane == 31) wsum[w] = sv;
    __syncthreads();
    if (w == 0) {
        int ws = wsum[lane];
        #pragma unroll
        for (int d = 1; d < 32; d <<= 1) {
            int u = __shfl_up_sync(0xFFFFFFFF, ws, d);
            if (lane >= d) ws += u;
        }
        wsum[lane] = ws;
    }
    __syncthreads();
    int wbase = (w > 0) ? wsum[w - 1] : 0;
    if (i < len) off[i] = wbase + sv - v;
    if (t == 1023) bsum[blockIdx.x] = wbase + sv;
}

__global__ void scan2_kernel()
{
    int lane = threadIdx.x & 31;
    int nb_e = (EE + 1023) >> 10, nb_n = (NN + 1023) >> 10;
    int* bsum = (threadIdx.x < 32) ? g_bsum_e : g_bsum_n;
    int nb    = (threadIdx.x < 32) ? nb_e : nb_n;
    int v = (lane < nb) ? bsum[lane] : 0;
    int sv = v;
    #pragma unroll
    for (int d = 1; d < 32; d <<= 1) {
        int u = __shfl_up_sync(0xFFFFFFFF, sv, d);
        if (lane >= d) sv += u;
    }
    if (lane < nb) bsum[lane] = sv - v;
    if (lane == 31) {
        if (threadIdx.x < 32) g_eoff[EE] = sv;
        else                  g_noff[NN] = sv;
    }
}

__global__ void scan3_kernel()
{
    int* off        = (blockIdx.y == 0) ? g_eoff : g_noff;
    const int* bsum = (blockIdx.y == 0) ? g_bsum_e : g_bsum_n;
    int len         = (blockIdx.y == 0) ? EE : NN;
    int i = blockIdx.x * 1024 + threadIdx.x;
    if (i < len) off[i] += bsum[blockIdx.x];
}

// ---------------- CSR fill ----------------
__global__ void fill_kernel(const int* __restrict__ ni, const int* __restrict__ ei)
{
    int k = blockIdx.x * blockDim.x + threadIdx.x;
    if (k >= NNZV) return;
    int n = ni[k], e = ei[k];
    int pe = atomicAdd(&g_ecur[e], 1);
    g_elist[g_eoff[e] + pe] = make_int2(k, n);
    int pn = atomicAdd(&g_ncur[n], 1);
    g_nlist[g_noff[n] + pn] = make_int2(k, e);
}

// ---------------- warp-per-edge gather ----------------
__global__ void edge_gather_kernel()
{
    int w = (blockIdx.x * blockDim.x + threadIdx.x) >> 5;
    int lane = threadIdx.x & 31;
    if (w >= EE) return;
    int s = g_eoff[w], t = g_eoff[w + 1];
    float be = (t > s) ? (1.0f / (float)(t - s)) : 0.f;
    int j = lane % DH, q = lane / DH;
    bool act = (lane < 30);

    float a[HID];
    #pragma unroll
    for (int h = 0; h < HID; h++) a[h] = 0.f;

    if (act) {
        for (int p = s + q; p < t; p += 5) {
            int2 kn = g_elist[p];
            float al = g_hsheaf[(size_t)kn.x * DH + j];
            const float* src = g_h0 + ((size_t)kn.y * DH + j) * ROW12;
            float4 v0 = *(const float4*)src;
            float4 v1 = *(const float4*)(src + 4);
            float  v2 = src[8];
            a[0] += al * v0.x; a[1] += al * v0.y; a[2] += al * v0.z; a[3] += al * v0.w;
            a[4] += al * v1.x; a[5] += al * v1.y; a[6] += al * v1.z; a[7] += al * v1.w;
            a[8] += al * v2;
        }
    }
    #pragma unroll
    for (int h = 0; h < HID; h++) {
        float v = a[h];
        float v6  = __shfl_down_sync(0xFFFFFFFF, v, 6);
        float v12 = __shfl_down_sync(0xFFFFFFFF, v, 12);
        float v18 = __shfl_down_sync(0xFFFFFFFF, v, 18);
        float v24 = __shfl_down_sync(0xFFFFFFFF, v, 24);
        a[h] = v + v6 + v12 + v18 + v24;
    }
    if (lane < DH) {
        float* dst = g_m + ((size_t)w * DH + j) * ROW12;
        *(float4*)dst       = make_float4(a[0] * be, a[1] * be, a[2] * be, a[3] * be);
        *(float4*)(dst + 4) = make_float4(a[4] * be, a[5] * be, a[6] * be, a[7] * be);
        dst[8] = a[8] * be;
    }
}

// ---------------- warp-per-node gather + finalize --------------------------------------
// l=0: ELU, then FUSED layer-1 h0 (LN + 9x9 matvec) written straight to g_h0.
// l=1: packed bf16 A' emit.
__global__ void node_gather_fin_kernel(const float* __restrict__ cbias, int l,
                                       const float* __restrict__ lng1,
                                       const float* __restrict__ lnb1,
                                       const float* __restrict__ cw1,
                                       const float* __restrict__ cb1)
{
    __shared__ float sW1[HID * HID], sg1[HID], sb1[HID], scb1[HID];
    {
        int t = threadIdx.x;
        for (int i = t; i < HID * HID; i += 256) sW1[i] = cw1[i];
        if (t < HID) { sg1[t] = lng1[t]; sb1[t] = lnb1[t]; scb1[t] = cb1[t]; }
    }
    __syncthreads();

    int w = (blockIdx.x * blockDim.x + threadIdx.x) >> 5;
    int lane = threadIdx.x & 31;
    if (w >= NN) return;
    int s = g_noff[w], t = g_noff[w + 1];
    float dv = (t > s) ? (1.0f / (float)(t - s)) : 0.f;
    int j = lane % DH, q = lane / DH;
    bool act = (lane < 30);

    float a[HID];
    #pragma unroll
    for (int h = 0; h < HID; h++) a[h] = 0.f;

    if (act) {
        for (int p = s + q; p < t; p += 5) {
            int2 ke = g_nlist[p];
            float al = g_hsheaf[(size_t)ke.x * DH + j];
            const float* src = g_m + ((size_t)ke.y * DH + j) * ROW12;
            float4 v0 = *(const float4*)src;
            float4 v1 = *(const float4*)(src + 4);
            float  v2 = src[8];
            a[0] += al * v0.x; a[1] += al * v0.y; a[2] += al * v0.z; a[3] += al * v0.w;
            a[4] += al * v1.x; a[5] += al * v1.y; a[6] += al * v1.z; a[7] += al * v1.w;
            a[8] += al * v2;
        }
    }
    #pragma unroll
    for (int h = 0; h < HID; h++) {
        float v = a[h];
        float v6  = __shfl_down_sync(0xFFFFFFFF, v, 6);
        float v12 = __shfl_down_sync(0xFFFFFFFF, v, 12);
        float v18 = __shfl_down_sync(0xFFFFFFFF, v, 18);
        float v24 = __shfl_down_sync(0xFFFFFFFF, v, 24);
        a[h] = v + v6 + v12 + v18 + v24;
    }

    if (lane < DH) {
        size_t idx = (size_t)w * DH + j;
        const float* h0r = g_h0 + idx * ROW12;
        float o[HID];
        #pragma unroll
        for (int h = 0; h < HID; h++)
            o[h] = a[h] * dv + h0r[h] + cbias[l * HID + h];

        if (l == 0) {
            // ELU, then fused layer-1 h0 for this row (all in registers)
            #pragma unroll
            for (int h = 0; h < HID; h++) {
                float v = o[h];
                o[h] = (v > 0.f) ? v : expm1f(v);
            }
            float mean = 0.f;
            #pragma unroll
            for (int h = 0; h < HID; h++) mean += o[h];
            mean *= (1.0f / HID);
            float var = 0.f;
            #pragma unroll
            for (int h = 0; h < HID; h++) { float d = o[h] - mean; var += d * d; }
            var *= (1.0f / HID);
            float rs = rsqrtf(var + 1e-5f);
            float y[HID];
            #pragma unroll
            for (int h = 0; h < HID; h++) y[h] = (o[h] - mean) * rs * sg1[h] + sb1[h];
            float* dst = g_h0 + idx * ROW12;
            #pragma unroll
            for (int c = 0; c < HID; c++) {
                float acc = scb1[c];
                #pragma unroll
                for (int h = 0; h < HID; h++) acc += y[h] * sW1[h * HID + c];
                dst[c] = acc;
            }
        } else {
            // packed A' row: [hi(54) | lo(54) | hi(54)], this thread owns cols j*9..j*9+8
            __nv_bfloat16* arow = g_Abf + (size_t)w * KTOT + j * HID;
            #pragma unroll
            for (int h = 0; h < HID; h++) {
                float v = o[h];
                __nv_bfloat16 hi = __float2bfloat16(v);
                __nv_bfloat16 lo = __float2bfloat16(v - __bfloat162float(hi));
                arow[h]            = hi;
                arow[PROJ + h]     = lo;
                arow[2 * PROJ + h] = hi;
            }
        }
    }
}

// ---------------- B' prep: packed [hi(54) | hi(54) | lo(54)], B[n][k] = W2[k][n] --------
__global__ void prep_B_kernel(const float* __restrict__ W2)
{
    int idx = blockIdx.x * blockDim.x + threadIdx.x;
    if (idx >= B_ROWS_PAD * KTOT) return;
    int n = idx / KTOT, k = idx - n * KTOT;
    __nv_bfloat16 o = __float2bfloat16(0.f);
    if (n < OUTD && k < KPACK) {
        int region = (k < PROJ) ? 0 : (k < 2 * PROJ) ? 1 : 2;
        int j = k - region * PROJ;
        float a = W2[(size_t)j * OUTD + n];
        __nv_bfloat16 h = __float2bfloat16(a);
        if (region == 2) o = __float2bfloat16(a - __bfloat162float(h));
        else             o = h;
    }
    g_Bbf[idx] = o;
}

// ---------------- HMMA lin2 GEMM v5: 128x256 tile, packed K=176, 2-stage chunk pipe ----
#define GTM 128
#define GTN 256
#define CST 72                              // chunk smem bf16 stride
#define STAGE_A (GTM * CST)                 // 9216 bf16
#define STAGE_ELEMS ((GTM + GTN) * CST)     // 27648 bf16 = 55296 B
#define GEMM_SMEM_BYTES (2 * STAGE_ELEMS * 2)   // 110592 B

#define LDSM_X4(r, addr) \
    asm volatile("ldmatrix.sync.aligned.m8n8.x4.shared.b16 {%0,%1,%2,%3}, [%4];" \
        : "=r"((r)[0]), "=r"((r)[1]), "=r"((r)[2]), "=r"((r)[3]) : "r"(addr))
#define MMA16816(d, a, b0, b1) \
    asm volatile("mma.sync.aligned.m16n8k16.row.col.f32.bf16.bf16.f32 " \
        "{%0,%1,%2,%3}, {%4,%5,%6,%7}, {%8,%9}, {%0,%1,%2,%3};" \
        : "+f"((d)[0]), "+f"((d)[1]), "+f"((d)[2]), "+f"((d)[3]) \
        : "r"((a)[0]), "r"((a)[1]), "r"((a)[2]), "r"((a)[3]), "r"(b0), "r"(b1))

__device__ __forceinline__ uint32_t smem_u32(const void* p) {
    uint32_t a;
    asm("{ .reg .u64 t; cvta.to.shared.u64 t, %1; cvt.u32.u64 %0, t; }" : "=r"(a) : "l"(p));
    return a;
}
__device__ __forceinline__ void cp16(uint32_t dst, const void* src) {
    asm volatile("cp.async.cg.shared.global [%0], [%1], 16;" :: "r"(dst), "l"(src));
}

__global__ void __launch_bounds__(512, 1)
lin2_mma_kernel(const float* __restrict__ bias, float* __restrict__ C)
{
    extern __shared__ __nv_bfloat16 smem[];
    __shared__ float sbias[GTN];

    int tid = threadIdx.x, lane = tid & 31, wid = tid >> 5;
    int wm = wid >> 2, wn = wid & 3;            // warp grid 4(M) x 4(N)
    int n0 = blockIdx.x * GTN, m0 = blockIdx.y * GTM;
    uint32_t smb = smem_u32(smem);

    // async load of chunk c (cols c*64..) into stage st; chunks are 64/64/48 cols
    auto load_chunk = [&](int c, int st) {
        int col = c * 64, nseg = (c == 2) ? 6 : 8;
        uint32_t base = smb + (uint32_t)(st * STAGE_ELEMS) * 2;
        for (int i = tid; i < GTM * nseg; i += 512) {
            int r = i / nseg, s = i - r * nseg;
            cp16(base + (uint32_t)(r * CST + s * 8) * 2,
                 g_Abf + (size_t)(m0 + r) * KTOT + col + s * 8);
        }
        uint32_t bb = base + (uint32_t)STAGE_A * 2;
        for (int i = tid; i < GTN * nseg; i += 512) {
            int r = i / nseg, s = i - r * nseg;
            cp16(bb + (uint32_t)(r * CST + s * 8) * 2,
                 g_Bbf + (size_t)(n0 + r) * KTOT + col + s * 8);
        }
        asm volatile("cp.async.commit_group;" ::: "memory");
    };

    load_chunk(0, 0);

    for (int i = tid; i < GTN; i += 512) {
        int n = n0 + i;
        sbias[i] = (n < OUTD) ? bias[n] : 0.f;
    }

    float acc[2][8][4];
    #pragma unroll
    for (int mt = 0; mt < 2; mt++)
        #pragma unroll
        for (int nt = 0; nt < 8; nt++)
            #pragma unroll
            for (int q = 0; q < 4; q++) acc[mt][nt][q] = 0.f;

    for (int c = 0; c < 3; c++) {
        if (c < 2) {
            load_chunk(c + 1, (c + 1) & 1);
            asm volatile("cp.async.wait_group 1;" ::: "memory");
        } else {
            asm volatile("cp.async.wait_group 0;" ::: "memory");
        }
        __syncthreads();

        uint32_t a_base = smb + (uint32_t)((c & 1) * STAGE_ELEMS) * 2;
        uint32_t b_base = a_base + (uint32_t)STAGE_A * 2;
        int nks = (c == 2) ? 3 : 4;

        #pragma unroll 4
        for (int ks = 0; ks < nks; ks++) {
            uint32_t af[2][4], bf[4][4];
            #pragma unroll
            for (int mt = 0; mt < 2; mt++) {
                int row = wm * 32 + mt * 16 + (lane & 15);
                int col = ks * 16 + (lane >> 4) * 8;
                LDSM_X4(af[mt], a_base + (uint32_t)(row * CST + col) * 2);
            }
            #pragma unroll
            for (int p = 0; p < 4; p++) {
                int q = lane >> 3, rl = lane & 7;
                int nrow = wn * 64 + p * 16 + (q >> 1) * 8 + rl;
                int col = ks * 16 + (q & 1) * 8;
                LDSM_X4(bf[p], b_base + (uint32_t)(nrow * CST + col) * 2);
            }
            #pragma unroll
            for (int mt = 0; mt < 2; mt++)
                #pragma unroll
                for (int nt = 0; nt < 8; nt++)
                    MMA16816(acc[mt][nt], af[mt],
                             bf[nt >> 1][(nt & 1) * 2], bf[nt >> 1][(nt & 1) * 2 + 1]);
        }
        __syncthreads();
    }

    // epilogue
    int gid = lane >> 2, tig = lane & 3;
    #pragma unroll
    for (int mt = 0; mt < 2; mt++) {
        int r0 = m0 + wm * 32 + mt * 16 + gid;
        int r1 = r0 + 8;
        #pragma unroll
        for (int nt = 0; nt < 8; nt++) {
            int lc = wn * 64 + nt * 8 + tig * 2;
            int c  = n0 + lc;
            if (c < OUTD) {
                float b0 = sbias[lc], b1 = sbias[lc + 1];
                if (r0 < NN) {
                    float2 v = make_float2(acc[mt][nt][0] + b0, acc[mt][nt][1] + b1);
                    *(float2*)(C + (size_t)r0 * OUTD + c) = v;
                }
                if (r1 < NN) {
                    float2 v = make_float2(acc[mt][nt][2] + b0, acc[mt][nt][3] + b1);
                    *(float2*)(C + (size_t)r1 * OUTD + c) = v;
                }
            }
        }
    }
}

// ---------------- launch ----------------
extern "C" void kernel_launch(void* const* d_in, const int* in_sizes, int n_in,
                              void* d_out, int out_size)
{
    const float* x        = (const float*)d_in[0];
    const float* hedge    = (const float*)d_in[1];
    const int*   node_idx = (const int*)  d_in[2];
    const int*   edge_idx = (const int*)  d_in[3];
    const float* lin_w    = (const float*)d_in[4];
    const float* lin_b    = (const float*)d_in[5];
    const float* s_ln_g   = (const float*)d_in[6];
    const float* s_ln_b   = (const float*)d_in[7];
    const float* sheaf_w  = (const float*)d_in[8];
    const float* sheaf_b  = (const float*)d_in[9];
    const float* c_ln_g   = (const float*)d_in[10];
    const float* c_ln_b   = (const float*)d_in[11];
    const float* conv_w   = (const float*)d_in[12];
    const float* conv_b   = (const float*)d_in[13];
    const float* conv_bias= (const float*)d_in[14];
    const float* lin2_w   = (const float*)d_in[15];
    const float* lin2_b   = (const float*)d_in[16];
    float* out = (float*)d_out;

    cudaFuncSetAttribute(lin2_mma_kernel,
                         cudaFuncAttributeMaxDynamicSharedMemorySize,
                         GEMM_SMEM_BYTES);

    zero_counts_kernel<<<(NN + 255) / 256, 256>>>();
    // proj + fused layer-0 h0 (16 rows/block)
    proj_kernel<<<(NN + EE + PBR - 1) / PBR, 64>>>(x, hedge, lin_w, lin_b,
                                                   c_ln_g, c_ln_b, conv_w, conv_b);
    sheaf_kernel<<<(NNZV + 255) / 256, 256>>>(node_idx, edge_idx,
                                              s_ln_g, s_ln_b, sheaf_w, sheaf_b);
    {
        dim3 g1((NN + 1023) / 1024, 2);
        scan1_kernel<<<g1, 1024>>>();
        scan2_kernel<<<1, 64>>>();
        scan3_kernel<<<g1, 1024>>>();
    }
    fill_kernel<<<(NNZV + 255) / 256, 256>>>(node_idx, edge_idx);
    prep_B_kernel<<<(B_ROWS_PAD * KTOT + 255) / 256, 256>>>(lin2_w);

    for (int l = 0; l < NLAY; l++) {
        edge_gather_kernel<<<(EE * 32 + 255) / 256, 256>>>();
        // l=0 fuses layer-1 h0 (LN/W/bias of layer 1 passed explicitly)
        node_gather_fin_kernel<<<(NN * 32 + 255) / 256, 256>>>(
            conv_bias, l,
            c_ln_g + HID, c_ln_b + HID, conv_w + HID * HID, conv_b + HID);
    }

    dim3 grid((OUTD + GTN - 1) / GTN, (NN + GTM - 1) / GTM);   // 20 x 157
    lin2_mma_kernel<<<grid, 512, GEMM_SMEM_BYTES>>>(lin2_b, out);
}

// round 15
// speedup vs baseline: 1.0893x; 1.0893x over previous
#include <cuda_runtime.h>
#include <cuda_bf16.h>
#include <math.h>
#include <stdint.h>

// ---------------- problem constants ----------------
#define NN    20000     // nodes
#define EE    5000      // hyperedges
#define NNZV  200000    // incidences
#define DH    6         // sheaf dim d
#define HID   9         // MLP hidden
#define FIN   256       // input features
#define OUTD  4968      // output dim
#define PROJ  54        // DH*HID
#define ROW12 12        // padded row stride (floats) for 9-wide rows
#define NLAY  2

// packed split-bf16 GEMM operand layout: [hi(54) | lo(54) | hi(54)] -> 162, pad to 176
#define KPACK   162
#define KTOT    176                  // 11 k16 steps, chunks [64|64|48]
#define A_ROWS_PAD 20096             // 157*128
#define B_ROWS_PAD 5120              // 20*256

// ---------------- scratch (static device globals; no runtime alloc) ----------------
// Device globals are zero-initialized at module load; padding regions of
// g_Abf/g_Bbf (cols 162..175, rows >= NN/OUTD) are never written -> stay zero.
__device__ __align__(16) float g_xm[NN * ROW12];
__device__ __align__(16) float g_em[EE * ROW12];
__device__ __align__(16) float g_hsheaf[(size_t)NNZV * DH];
__device__ int   g_cnt_node[NN];
__device__ int   g_cnt_edge[EE];
__device__ int   g_noff[NN + 1];
__device__ int   g_eoff[EE + 1];
__device__ int   g_ncur[NN];
__device__ int   g_ecur[EE];
__device__ int   g_bsum_e[32];
__device__ int   g_bsum_n[32];
__device__ __align__(8) int2 g_elist[NNZV];   // (k, node)
__device__ __align__(8) int2 g_nlist[NNZV];   // (k, edge)
__device__ __align__(16) float g_h0[(size_t)NN * DH * ROW12];
__device__ __align__(16) float g_m[(size_t)EE * DH * ROW12];
__device__ __align__(16) __nv_bfloat16 g_Abf[(size_t)A_ROWS_PAD * KTOT];  // 7.1 MB
__device__ __align__(16) __nv_bfloat16 g_Bbf[(size_t)B_ROWS_PAD * KTOT];  // 1.8 MB

// ---------------- zero counts + cursors ----------------
__global__ void zero_counts_kernel() {
    int i = blockIdx.x * blockDim.x + threadIdx.x;
    if (i < NN) { g_cnt_node[i] = 0; g_ncur[i] = 0; }
    if (i < EE) { g_cnt_edge[i] = 0; g_ecur[i] = 0; }
}

// ---------------- input projection + per-row mean + FUSED layer-0 h0 ----------------
// 8 rows per block, 64 threads (R12-proven config)
__global__ void proj_kernel(const float* __restrict__ x,
                            const float* __restrict__ ha,
                            const float* __restrict__ W,
                            const float* __restrict__ b,
                            const float* __restrict__ lng0,   // conv LN gamma, layer 0
                            const float* __restrict__ lnb0,   // conv LN beta, layer 0
                            const float* __restrict__ cw0,    // conv W, layer 0 (9x9)
                            const float* __restrict__ cb0)    // conv b, layer 0
{
    __shared__ float sx[8][FIN];
    __shared__ float sout[8][PROJ];
    __shared__ float sW0[HID * HID], sg0[HID], sb0[HID], scb0[HID];
    int r0 = blockIdx.x * 8;
    int t  = threadIdx.x;

    for (int i = t; i < HID * HID; i += 64) sW0[i] = cw0[i];
    if (t < HID) { sg0[t] = lng0[t]; sb0[t] = lnb0[t]; scb0[t] = cb0[t]; }

    #pragma unroll
    for (int rr = 0; rr < 8; rr++) {
        int r = r0 + rr;
        if (r >= NN + EE) break;
        const float* src = (r < NN) ? (x + (size_t)r * FIN) : (ha + (size_t)(r - NN) * FIN);
        for (int c = t; c < FIN; c += 64) sx[rr][c] = src[c];
    }
    __syncthreads();

    if (t < PROJ) {
        float acc[8];
        float bt = b[t];
        #pragma unroll
        for (int rr = 0; rr < 8; rr++) acc[rr] = bt;
        #pragma unroll 4
        for (int c = 0; c < FIN; c++) {
            float w = W[c * PROJ + t];
            #pragma unroll
            for (int rr = 0; rr < 8; rr++) acc[rr] += w * sx[rr][c];
        }
        #pragma unroll
        for (int rr = 0; rr < 8; rr++) {
            int r = r0 + rr;
            if (r >= NN + EE) break;
            sout[rr][t] = acc[rr];
        }
    }
    __syncthreads();

    // per-row mean over d (for sheaf builder)
    if (t < HID) {
        #pragma unroll
        for (int rr = 0; rr < 8; rr++) {
            int r = r0 + rr;
            if (r >= NN + EE) break;
            float s = 0.f;
            #pragma unroll
            for (int j = 0; j < DH; j++) s += sout[rr][j * HID + t];
            s *= (1.0f / DH);
            if (r < NN) g_xm[(size_t)r * ROW12 + t] = s;
            else        g_em[(size_t)(r - NN) * ROW12 + t] = s;
        }
    }

    // fused layer-0 h0 (node rows only)
    if (t < PROJ) {
        int j = t / HID, c = t - (t / HID) * HID;
        #pragma unroll
        for (int rr = 0; rr < 8; rr++) {
            int r = r0 + rr;
            if (r >= NN) break;
            float v[HID];
            #pragma unroll
            for (int h = 0; h < HID; h++) v[h] = sout[rr][j * HID + h];
            float mean = 0.f;
            #pragma unroll
            for (int h = 0; h < HID; h++) mean += v[h];
            mean *= (1.0f / HID);
            float var = 0.f;
            #pragma unroll
            for (int h = 0; h < HID; h++) { float d = v[h] - mean; var += d * d; }
            var *= (1.0f / HID);
            float rs = rsqrtf(var + 1e-5f);
            float acc = scb0[c];
            #pragma unroll
            for (int h = 0; h < HID; h++)
                acc += ((v[h] - mean) * rs * sg0[h] + sb0[h]) * sW0[h * HID + c];
            g_h0[((size_t)r * DH + j) * ROW12 + c] = acc;
        }
    }
}

// ---------------- sheaf builder (alpha + degree counts) ----------------
__global__ void sheaf_kernel(const int* __restrict__ ni, const int* __restrict__ ei,
                             const float* __restrict__ lng, const float* __restrict__ lnb,
                             const float* __restrict__ sw,  const float* __restrict__ sb)
{
    __shared__ float s_sw[2 * HID * DH];
    __shared__ float s_sb[DH];
    __shared__ float s_g[2 * HID], s_b[2 * HID];
    int t = threadIdx.x;
    if (t < 2 * HID * DH) s_sw[t] = sw[t];
    if (t < DH) s_sb[t] = sb[t];
    if (t < 2 * HID) { s_g[t] = lng[t]; s_b[t] = lnb[t]; }
    __syncthreads();

    int k = blockIdx.x * blockDim.x + threadIdx.x;
    if (k >= NNZV) return;
    int n = ni[k], e = ei[k];

    float v[2 * HID];
    {
        const float4 a0 = *(const float4*)(g_xm + (size_t)n * ROW12);
        const float4 a1 = *(const float4*)(g_xm + (size_t)n * ROW12 + 4);
        v[0]=a0.x; v[1]=a0.y; v[2]=a0.z; v[3]=a0.w;
        v[4]=a1.x; v[5]=a1.y; v[6]=a1.z; v[7]=a1.w;
        v[8] = g_xm[(size_t)n * ROW12 + 8];
        const float4 b0 = *(const float4*)(g_em + (size_t)e * ROW12);
        const float4 b1 = *(const float4*)(g_em + (size_t)e * ROW12 + 4);
        v[9]=b0.x; v[10]=b0.y; v[11]=b0.z; v[12]=b0.w;
        v[13]=b1.x; v[14]=b1.y; v[15]=b1.z; v[16]=b1.w;
        v[17] = g_em[(size_t)e * ROW12 + 8];
    }
    float mean = 0.f;
    #pragma unroll
    for (int i = 0; i < 18; i++) mean += v[i];
    mean *= (1.0f / 18.0f);
    float var = 0.f;
    #pragma unroll
    for (int i = 0; i < 18; i++) { float d = v[i] - mean; var += d * d; }
    var *= (1.0f / 18.0f);
    float rs = rsqrtf(var + 1e-5f);
    float y[18];
    #pragma unroll
    for (int i = 0; i < 18; i++) y[i] = (v[i] - mean) * rs * s_g[i] + s_b[i];

    #pragma unroll
    for (int j = 0; j < DH; j++) {
        float z = s_sb[j];
        #pragma unroll
        for (int i = 0; i < 18; i++) z += y[i] * s_sw[i * DH + j];
        float h = 1.0f / (1.0f + __expf(-z));
        g_hsheaf[(size_t)k * DH + j] = h;
    }
    atomicAdd(&g_cnt_node[n], 1);
    atomicAdd(&g_cnt_edge[e], 1);
}

// ---------------- hierarchical scan (3 stages) ----------------
__global__ void scan1_kernel()
{
    __shared__ int wsum[32];
    const int* cnt = (blockIdx.y == 0) ? g_cnt_edge : g_cnt_node;
    int* off       = (blockIdx.y == 0) ? g_eoff : g_noff;
    int* bsum      = (blockIdx.y == 0) ? g_bsum_e : g_bsum_n;
    int len        = (blockIdx.y == 0) ? EE : NN;
    int nblk       = (len + 1023) >> 10;
    if (blockIdx.x >= nblk) return;

    int t = threadIdx.x, lane = t & 31, w = t >> 5;
    int i = blockIdx.x * 1024 + t;
    int v = (i < len) ? cnt[i] : 0;

    int sv = v;
    #pragma unroll
    for (int d = 1; d < 32; d <<= 1) {
        int u = __shfl_up_sync(0xFFFFFFFF, sv, d);
        if (lane >= d) sv += u;
    }
    if (lane == 31) wsum[w] = sv;
    __syncthreads();
    if (w == 0) {
        int ws = wsum[lane];
        #pragma unroll
        for (int d = 1; d < 32; d <<= 1) {
            int u = __shfl_up_sync(0xFFFFFFFF, ws, d);
            if (lane >= d) ws += u;
        }
        wsum[lane] = ws;
    }
    __syncthreads();
    int wbase = (w > 0) ? wsum[w - 1] : 0;
    if (i < len) off[i] = wbase + sv - v;
    if (t == 1023) bsum[blockIdx.x] = wbase + sv;
}

__global__ void scan2_kernel()
{
    int lane = threadIdx.x & 31;
    int nb_e = (EE + 1023) >> 10, nb_n = (NN + 1023) >> 10;
    int* bsum = (threadIdx.x < 32) ? g_bsum_e : g_bsum_n;
    int nb    = (threadIdx.x < 32) ? nb_e : nb_n;
    int v = (lane < nb) ? bsum[lane] : 0;
    int sv = v;
    #pragma unroll
    for (int d = 1; d < 32; d <<= 1) {
        int u = __shfl_up_sync(0xFFFFFFFF, sv, d);
        if (lane >= d) sv += u;
    }
    if (lane < nb) bsum[lane] = sv - v;
    if (lane == 31) {
        if (threadIdx.x < 32) g_eoff[EE] = sv;
        else                  g_noff[NN] = sv;
    }
}

__global__ void scan3_kernel()
{
    int* off        = (blockIdx.y == 0) ? g_eoff : g_noff;
    const int* bsum = (blockIdx.y == 0) ? g_bsum_e : g_bsum_n;
    int len         = (blockIdx.y == 0) ? EE : NN;
    int i = blockIdx.x * 1024 + threadIdx.x;
    if (i < len) off[i] += bsum[blockIdx.x];
}

// ---------------- CSR fill ----------------
__global__ void fill_kernel(const int* __restrict__ ni, const int* __restrict__ ei)
{
    int k = blockIdx.x * blockDim.x + threadIdx.x;
    if (k >= NNZV) return;
    int n = ni[k], e = ei[k];
    int pe = atomicAdd(&g_ecur[e], 1);
    g_elist[g_eoff[e] + pe] = make_int2(k, n);
    int pn = atomicAdd(&g_ncur[n], 1);
    g_nlist[g_noff[n] + pn] = make_int2(k, e);
}

// ---------------- warp-per-edge gather ----------------
__global__ void edge_gather_kernel()
{
    int w = (blockIdx.x * blockDim.x + threadIdx.x) >> 5;
    int lane = threadIdx.x & 31;
    if (w >= EE) return;
    int s = g_eoff[w], t = g_eoff[w + 1];
    float be = (t > s) ? (1.0f / (float)(t - s)) : 0.f;
    int j = lane % DH, q = lane / DH;
    bool act = (lane < 30);

    float a[HID];
    #pragma unroll
    for (int h = 0; h < HID; h++) a[h] = 0.f;

    if (act) {
        for (int p = s + q; p < t; p += 5) {
            int2 kn = g_elist[p];
            float al = g_hsheaf[(size_t)kn.x * DH + j];
            const float* src = g_h0 + ((size_t)kn.y * DH + j) * ROW12;
            float4 v0 = *(const float4*)src;
            float4 v1 = *(const float4*)(src + 4);
            float  v2 = src[8];
            a[0] += al * v0.x; a[1] += al * v0.y; a[2] += al * v0.z; a[3] += al * v0.w;
            a[4] += al * v1.x; a[5] += al * v1.y; a[6] += al * v1.z; a[7] += al * v1.w;
            a[8] += al * v2;
        }
    }
    #pragma unroll
    for (int h = 0; h < HID; h++) {
        float v = a[h];
        float v6  = __shfl_down_sync(0xFFFFFFFF, v, 6);
        float v12 = __shfl_down_sync(0xFFFFFFFF, v, 12);
        float v18 = __shfl_down_sync(0xFFFFFFFF, v, 18);
        float v24 = __shfl_down_sync(0xFFFFFFFF, v, 24);
        a[h] = v + v6 + v12 + v18 + v24;
    }
    if (lane < DH) {
        float* dst = g_m + ((size_t)w * DH + j) * ROW12;
        *(float4*)dst       = make_float4(a[0] * be, a[1] * be, a[2] * be, a[3] * be);
        *(float4*)(dst + 4) = make_float4(a[4] * be, a[5] * be, a[6] * be, a[7] * be);
        dst[8] = a[8] * be;
    }
}

// ---------------- warp-per-node gather + finalize --------------------------------------
// l=0: ELU, then FUSED layer-1 h0 (LN + 9x9 matvec) written straight to g_h0
//      (weight staging guarded by l==0 -> zero overhead on the l=1 invocation).
// l=1: packed bf16 A' emit.
__global__ void node_gather_fin_kernel(const float* __restrict__ cbias, int l,
                                       const float* __restrict__ lng1,
                                       const float* __restrict__ lnb1,
                                       const float* __restrict__ cw1,
                                       const float* __restrict__ cb1)
{
    __shared__ float sW1[HID * HID], sg1[HID], sb1[HID], scb1[HID];
    if (l == 0) {   // uniform branch across grid
        int t = threadIdx.x;
        for (int i = t; i < HID * HID; i += 256) sW1[i] = cw1[i];
        if (t < HID) { sg1[t] = lng1[t]; sb1[t] = lnb1[t]; scb1[t] = cb1[t]; }
        __syncthreads();
    }

    int w = (blockIdx.x * blockDim.x + threadIdx.x) >> 5;
    int lane = threadIdx.x & 31;
    if (w >= NN) return;
    int s = g_noff[w], t = g_noff[w + 1];
    float dv = (t > s) ? (1.0f / (float)(t - s)) : 0.f;
    int j = lane % DH, q = lane / DH;
    bool act = (lane < 30);

    float a[HID];
    #pragma unroll
    for (int h = 0; h < HID; h++) a[h] = 0.f;

    if (act) {
        for (int p = s + q; p < t; p += 5) {
            int2 ke = g_nlist[p];
            float al = g_hsheaf[(size_t)ke.x * DH + j];
            const float* src = g_m + ((size_t)ke.y * DH + j) * ROW12;
            float4 v0 = *(const float4*)src;
            float4 v1 = *(const float4*)(src + 4);
            float  v2 = src[8];
            a[0] += al * v0.x; a[1] += al * v0.y; a[2] += al * v0.z; a[3] += al * v0.w;
            a[4] += al * v1.x; a[5] += al * v1.y; a[6] += al * v1.z; a[7] += al * v1.w;
            a[8] += al * v2;
        }
    }
    #pragma unroll
    for (int h = 0; h < HID; h++) {
        float v = a[h];
        float v6  = __shfl_down_sync(0xFFFFFFFF, v, 6);
        float v12 = __shfl_down_sync(0xFFFFFFFF, v, 12);
        float v18 = __shfl_down_sync(0xFFFFFFFF, v, 18);
        float v24 = __shfl_down_sync(0xFFFFFFFF, v, 24);
        a[h] = v + v6 + v12 + v18 + v24;
    }

    if (lane < DH) {
        size_t idx = (size_t)w * DH + j;
        const float* h0r = g_h0 + idx * ROW12;
        float o[HID];
        #pragma unroll
        for (int h = 0; h < HID; h++)
            o[h] = a[h] * dv + h0r[h] + cbias[l * HID + h];

        if (l == 0) {
            // ELU, then fused layer-1 h0 for this row (all in registers)
            #pragma unroll
            for (int h = 0; h < HID; h++) {
                float v = o[h];
                o[h] = (v > 0.f) ? v : expm1f(v);
            }
            float mean = 0.f;
            #pragma unroll
            for (int h = 0; h < HID; h++) mean += o[h];
            mean *= (1.0f / HID);
            float var = 0.f;
            #pragma unroll
            for (int h = 0; h < HID; h++) { float d = o[h] - mean; var += d * d; }
            var *= (1.0f / HID);
            float rs = rsqrtf(var + 1e-5f);
            float y[HID];
            #pragma unroll
            for (int h = 0; h < HID; h++) y[h] = (o[h] - mean) * rs * sg1[h] + sb1[h];
            float* dst = g_h0 + idx * ROW12;
            #pragma unroll
            for (int c = 0; c < HID; c++) {
                float acc = scb1[c];
                #pragma unroll
                for (int h = 0; h < HID; h++) acc += y[h] * sW1[h * HID + c];
                dst[c] = acc;
            }
        } else {
            // packed A' row: [hi(54) | lo(54) | hi(54)], this thread owns cols j*9..j*9+8
            __nv_bfloat16* arow = g_Abf + (size_t)w * KTOT + j * HID;
            #pragma unroll
            for (int h = 0; h < HID; h++) {
                float v = o[h];
                __nv_bfloat16 hi = __float2bfloat16(v);
                __nv_bfloat16 lo = __float2bfloat16(v - __bfloat162float(hi));
                arow[h]            = hi;
                arow[PROJ + h]     = lo;
                arow[2 * PROJ + h] = hi;
            }
        }
    }
}

// ---------------- B' prep: packed [hi(54) | hi(54) | lo(54)], B[n][k] = W2[k][n] --------
__global__ void prep_B_kernel(const float* __restrict__ W2)
{
    int idx = blockIdx.x * blockDim.x + threadIdx.x;
    if (idx >= B_ROWS_PAD * KTOT) return;
    int n = idx / KTOT, k = idx - n * KTOT;
    __nv_bfloat16 o = __float2bfloat16(0.f);
    if (n < OUTD && k < KPACK) {
        int region = (k < PROJ) ? 0 : (k < 2 * PROJ) ? 1 : 2;
        int j = k - region * PROJ;
        float a = W2[(size_t)j * OUTD + n];
        __nv_bfloat16 h = __float2bfloat16(a);
        if (region == 2) o = __float2bfloat16(a - __bfloat162float(h));
        else             o = h;
    }
    g_Bbf[idx] = o;
}

// ---------------- HMMA lin2 GEMM v5: 128x256 tile, packed K=176, 2-stage chunk pipe ----
#define GTM 128
#define GTN 256
#define CST 72                              // chunk smem bf16 stride
#define STAGE_A (GTM * CST)                 // 9216 bf16
#define STAGE_ELEMS ((GTM + GTN) * CST)     // 27648 bf16 = 55296 B
#define GEMM_SMEM_BYTES (2 * STAGE_ELEMS * 2)   // 110592 B

#define LDSM_X4(r, addr) \
    asm volatile("ldmatrix.sync.aligned.m8n8.x4.shared.b16 {%0,%1,%2,%3}, [%4];" \
        : "=r"((r)[0]), "=r"((r)[1]), "=r"((r)[2]), "=r"((r)[3]) : "r"(addr))
#define MMA16816(d, a, b0, b1) \
    asm volatile("mma.sync.aligned.m16n8k16.row.col.f32.bf16.bf16.f32 " \
        "{%0,%1,%2,%3}, {%4,%5,%6,%7}, {%8,%9}, {%0,%1,%2,%3};" \
        : "+f"((d)[0]), "+f"((d)[1]), "+f"((d)[2]), "+f"((d)[3]) \
        : "r"((a)[0]), "r"((a)[1]), "r"((a)[2]), "r"((a)[3]), "r"(b0), "r"(b1))

__device__ __forceinline__ uint32_t smem_u32(const void* p) {
    uint32_t a;
    asm("{ .reg .u64 t; cvta.to.shared.u64 t, %1; cvt.u32.u64 %0, t; }" : "=r"(a) : "l"(p));
    return a;
}
__device__ __forceinline__ void cp16(uint32_t dst, const void* src) {
    asm volatile("cp.async.cg.shared.global [%0], [%1], 16;" :: "r"(dst), "l"(src));
}

__global__ void __launch_bounds__(512, 1)
lin2_mma_kernel(const float* __restrict__ bias, float* __restrict__ C)
{
    extern __shared__ __nv_bfloat16 smem[];
    __shared__ float sbias[GTN];

    int tid = threadIdx.x, lane = tid & 31, wid = tid >> 5;
    int wm = wid >> 2, wn = wid & 3;            // warp grid 4(M) x 4(N)
    int n0 = blockIdx.x * GTN, m0 = blockIdx.y * GTM;
    uint32_t smb = smem_u32(smem);

    // async load of chunk c (cols c*64..) into stage st; chunks are 64/64/48 cols
    auto load_chunk = [&](int c, int st) {
        int col = c * 64, nseg = (c == 2) ? 6 : 8;
        uint32_t base = smb + (uint32_t)(st * STAGE_ELEMS) * 2;
        for (int i = tid; i < GTM * nseg; i += 512) {
            int r = i / nseg, s = i - r * nseg;
            cp16(base + (uint32_t)(r * CST + s * 8) * 2,
                 g_Abf + (size_t)(m0 + r) * KTOT + col + s * 8);
        }
        uint32_t bb = base + (uint32_t)STAGE_A * 2;
        for (int i = tid; i < GTN * nseg; i += 512) {
            int r = i / nseg, s = i - r * nseg;
            cp16(bb + (uint32_t)(r * CST + s * 8) * 2,
                 g_Bbf + (size_t)(n0 + r) * KTOT + col + s * 8);
        }
        asm volatile("cp.async.commit_group;" ::: "memory");
    };

    load_chunk(0, 0);

    for (int i = tid; i < GTN; i += 512) {
        int n = n0 + i;
        sbias[i] = (n < OUTD) ? bias[n] : 0.f;
    }

    float acc[2][8][4];
    #pragma unroll
    for (int mt = 0; mt < 2; mt++)
        #pragma unroll
        for (int nt = 0; nt < 8; nt++)
            #pragma unroll
            for (int q = 0; q < 4; q++) acc[mt][nt][q] = 0.f;

    for (int c = 0; c < 3; c++) {
        if (c < 2) {
            load_chunk(c + 1, (c + 1) & 1);
            asm volatile("cp.async.wait_group 1;" ::: "memory");
        } else {
            asm volatile("cp.async.wait_group 0;" ::: "memory");
        }
        __syncthreads();

        uint32_t a_base = smb + (uint32_t)((c & 1) * STAGE_ELEMS) * 2;
        uint32_t b_base = a_base + (uint32_t)STAGE_A * 2;
        int nks = (c == 2) ? 3 : 4;

        #pragma unroll 4
        for (int ks = 0; ks < nks; ks++) {
            uint32_t af[2][4], bf[4][4];
            #pragma unroll
            for (int mt = 0; mt < 2; mt++) {
                int row = wm * 32 + mt * 16 + (lane & 15);
                int col = ks * 16 + (lane >> 4) * 8;
                LDSM_X4(af[mt], a_base + (uint32_t)(row * CST + col) * 2);
            }
            #pragma unroll
            for (int p = 0; p < 4; p++) {
                int q = lane >> 3, rl = lane & 7;
                int nrow = wn * 64 + p * 16 + (q >> 1) * 8 + rl;
                int col = ks * 16 + (q & 1) * 8;
                LDSM_X4(bf[p], b_base + (uint32_t)(nrow * CST + col) * 2);
            }
            #pragma unroll
            for (int mt = 0; mt < 2; mt++)
                #pragma unroll
                for (int nt = 0; nt < 8; nt++)
                    MMA16816(acc[mt][nt], af[mt],
                             bf[nt >> 1][(nt & 1) * 2], bf[nt >> 1][(nt & 1) * 2 + 1]);
        }
        __syncthreads();
    }

    // epilogue
    int gid = lane >> 2, tig = lane & 3;
    #pragma unroll
    for (int mt = 0; mt < 2; mt++) {
        int r0 = m0 + wm * 32 + mt * 16 + gid;
        int r1 = r0 + 8;
        #pragma unroll
        for (int nt = 0; nt < 8; nt++) {
            int lc = wn * 64 + nt * 8 + tig * 2;
            int c  = n0 + lc;
            if (c < OUTD) {
                float b0 = sbias[lc], b1 = sbias[lc + 1];
                if (r0 < NN) {
                    float2 v = make_float2(acc[mt][nt][0] + b0, acc[mt][nt][1] + b1);
                    *(float2*)(C + (size_t)r0 * OUTD + c) = v;
                }
                if (r1 < NN) {
                    float2 v = make_float2(acc[mt][nt][2] + b0, acc[mt][nt][3] + b1);
                    *(float2*)(C + (size_t)r1 * OUTD + c) = v;
                }
            }
        }
    }
}

// ---------------- launch ----------------
extern "C" void kernel_launch(void* const* d_in, const int* in_sizes, int n_in,
                              void* d_out, int out_size)
{
    const float* x        = (const float*)d_in[0];
    const float* hedge    = (const float*)d_in[1];
    const int*   node_idx = (const int*)  d_in[2];
    const int*   edge_idx = (const int*)  d_in[3];
    const float* lin_w    = (const float*)d_in[4];
    const float* lin_b    = (const float*)d_in[5];
    const float* s_ln_g   = (const float*)d_in[6];
    const float* s_ln_b   = (const float*)d_in[7];
    const float* sheaf_w  = (const float*)d_in[8];
    const float* sheaf_b  = (const float*)d_in[9];
    const float* c_ln_g   = (const float*)d_in[10];
    const float* c_ln_b   = (const float*)d_in[11];
    const float* conv_w   = (const float*)d_in[12];
    const float* conv_b   = (const float*)d_in[13];
    const float* conv_bias= (const float*)d_in[14];
    const float* lin2_w   = (const float*)d_in[15];
    const float* lin2_b   = (const float*)d_in[16];
    float* out = (float*)d_out;

    cudaFuncSetAttribute(lin2_mma_kernel,
                         cudaFuncAttributeMaxDynamicSharedMemorySize,
                         GEMM_SMEM_BYTES);

    zero_counts_kernel<<<(NN + 255) / 256, 256>>>();
    // proj + fused layer-0 h0 (8 rows/block, R12 config)
    proj_kernel<<<(NN + EE + 7) / 8, 64>>>(x, hedge, lin_w, lin_b,
                                           c_ln_g, c_ln_b, conv_w, conv_b);
    sheaf_kernel<<<(NNZV + 255) / 256, 256>>>(node_idx, edge_idx,
                                              s_ln_g, s_ln_b, sheaf_w, sheaf_b);
    {
        dim3 g1((NN + 1023) / 1024, 2);
        scan1_kernel<<<g1, 1024>>>();
        scan2_kernel<<<1, 64>>>();
        scan3_kernel<<<g1, 1024>>>();
    }
    fill_kernel<<<(NNZV + 255) / 256, 256>>>(node_idx, edge_idx);
    prep_B_kernel<<<(B_ROWS_PAD * KTOT + 255) / 256, 256>>>(lin2_w);

    for (int l = 0; l < NLAY; l++) {
        edge_gather_kernel<<<(EE * 32 + 255) / 256, 256>>>();
        // l=0 fuses layer-1 h0 (LN/W/bias of layer 1 passed explicitly)
        node_gather_fin_kernel<<<(NN * 32 + 255) / 256, 256>>>(
            conv_bias, l,
            c_ln_g + HID, c_ln_b + HID, conv_w + HID * HID, conv_b + HID);
    }

    dim3 grid((OUTD + GTN - 1) / GTN, (NN + GTM - 1) / GTM);   // 20 x 157
    lin2_mma_kernel<<<grid, 512, GEMM_SMEM_BYTES>>>(lin2_b, out);
}

// round 16
// speedup vs baseline: 1.1219x; 1.0299x over previous
#include <cuda_runtime.h>
#include <cuda_bf16.h>
#include <math.h>
#include <stdint.h>

// ---------------- problem constants ----------------
#define NN    20000     // nodes
#define EE    5000      // hyperedges
#define NNZV  200000    // incidences
#define DH    6         // sheaf dim d
#define HID   9         // MLP hidden
#define FIN   256       // input features
#define OUTD  4968      // output dim
#define PROJ  54        // DH*HID
#define ROW12 12        // padded row stride (floats) for 9-wide rows
#define NLAY  2

// packed split-bf16 GEMM operand layout: [hi(54) | lo(54) | hi(54)] -> 162, pad to 176
#define KPACK   162
#define KTOT    176                  // 11 k16 steps, chunks [64|64|48]
#define A_ROWS_PAD 20096             // 157*128
#define B_ROWS_PAD 5120              // 20*256

#define SHEAF_BLKS ((NNZV + 255) / 256)              // 782
#define PREPB_BLKS ((B_ROWS_PAD * KTOT + 255) / 256) // 3520

// ---------------- scratch (static device globals; no runtime alloc) ----------------
// Device globals are zero-initialized at module load; padding regions of
// g_Abf/g_Bbf (cols 162..175, rows >= NN/OUTD) are never written -> stay zero.
__device__ __align__(16) float g_xproj[NN * PROJ];   // x-state between layers
__device__ __align__(16) float g_xm[NN * ROW12];
__device__ __align__(16) float g_em[EE * ROW12];
__device__ __align__(16) float g_hsheaf[(size_t)NNZV * DH];
__device__ int   g_cnt_node[NN];
__device__ int   g_cnt_edge[EE];
__device__ int   g_noff[NN + 1];
__device__ int   g_eoff[EE + 1];
__device__ int   g_ncur[NN];
__device__ int   g_ecur[EE];
__device__ int   g_bsum_e[32];
__device__ int   g_bsum_n[32];
__device__ __align__(8) int2 g_elist[NNZV];   // (k, node)
__device__ __align__(8) int2 g_nlist[NNZV];   // (k, edge)
__device__ __align__(16) float g_h0[(size_t)NN * DH * ROW12];
__device__ __align__(16) float g_m[(size_t)EE * DH * ROW12];
__device__ __align__(16) __nv_bfloat16 g_Abf[(size_t)A_ROWS_PAD * KTOT];  // 7.1 MB
__device__ __align__(16) __nv_bfloat16 g_Bbf[(size_t)B_ROWS_PAD * KTOT];  // 1.8 MB

// ---------------- input projection + per-row mean + FUSED layer-0 h0 + count zeroing ----
// 8 rows per block, 64 threads (R12-proven config)
__global__ void proj_kernel(const float* __restrict__ x,
                            const float* __restrict__ ha,
                            const float* __restrict__ W,
                            const float* __restrict__ b,
                            const float* __restrict__ lng0,   // conv LN gamma, layer 0
                            const float* __restrict__ lnb0,   // conv LN beta, layer 0
                            const float* __restrict__ cw0,    // conv W, layer 0 (9x9)
                            const float* __restrict__ cb0)    // conv b, layer 0
{
    __shared__ float sx[8][FIN];
    __shared__ float sout[8][PROJ];
    __shared__ float sW0[HID * HID], sg0[HID], sb0[HID], scb0[HID];
    int r0 = blockIdx.x * 8;
    int t  = threadIdx.x;

    // fused count/cursor zeroing (read later by sheaf/fill, after this kernel)
    {
        int gid = blockIdx.x * 64 + t;
        if (gid < NN) { g_cnt_node[gid] = 0; g_ncur[gid] = 0; }
        if (gid < EE) { g_cnt_edge[gid] = 0; g_ecur[gid] = 0; }
    }

    for (int i = t; i < HID * HID; i += 64) sW0[i] = cw0[i];
    if (t < HID) { sg0[t] = lng0[t]; sb0[t] = lnb0[t]; scb0[t] = cb0[t]; }

    #pragma unroll
    for (int rr = 0; rr < 8; rr++) {
        int r = r0 + rr;
        if (r >= NN + EE) break;
        const float* src = (r < NN) ? (x + (size_t)r * FIN) : (ha + (size_t)(r - NN) * FIN);
        for (int c = t; c < FIN; c += 64) sx[rr][c] = src[c];
    }
    __syncthreads();

    if (t < PROJ) {
        float acc[8];
        float bt = b[t];
        #pragma unroll
        for (int rr = 0; rr < 8; rr++) acc[rr] = bt;
        #pragma unroll 4
        for (int c = 0; c < FIN; c++) {
            float w = W[c * PROJ + t];
            #pragma unroll
            for (int rr = 0; rr < 8; rr++) acc[rr] += w * sx[rr][c];
        }
        #pragma unroll
        for (int rr = 0; rr < 8; rr++) {
            int r = r0 + rr;
            if (r >= NN + EE) break;
            sout[rr][t] = acc[rr];   // g_xproj store dropped: dead (overwritten at l=0 finalize)
        }
    }
    __syncthreads();

    // per-row mean over d (for sheaf builder)
    if (t < HID) {
        #pragma unroll
        for (int rr = 0; rr < 8; rr++) {
            int r = r0 + rr;
            if (r >= NN + EE) break;
            float s = 0.f;
            #pragma unroll
            for (int j = 0; j < DH; j++) s += sout[rr][j * HID + t];
            s *= (1.0f / DH);
            if (r < NN) g_xm[(size_t)r * ROW12 + t] = s;
            else        g_em[(size_t)(r - NN) * ROW12 + t] = s;
        }
    }

    // fused layer-0 h0 (node rows only)
    if (t < PROJ) {
        int j = t / HID, c = t - (t / HID) * HID;
        #pragma unroll
        for (int rr = 0; rr < 8; rr++) {
            int r = r0 + rr;
            if (r >= NN) break;
            float v[HID];
            #pragma unroll
            for (int h = 0; h < HID; h++) v[h] = sout[rr][j * HID + h];
            float mean = 0.f;
            #pragma unroll
            for (int h = 0; h < HID; h++) mean += v[h];
            mean *= (1.0f / HID);
            float var = 0.f;
            #pragma unroll
            for (int h = 0; h < HID; h++) { float d = v[h] - mean; var += d * d; }
            var *= (1.0f / HID);
            float rs = rsqrtf(var + 1e-5f);
            float acc = scb0[c];
            #pragma unroll
            for (int h = 0; h < HID; h++)
                acc += ((v[h] - mean) * rs * sg0[h] + sb0[h]) * sW0[h * HID + c];
            g_h0[((size_t)r * DH + j) * ROW12 + c] = acc;
        }
    }
}

// ---------------- sheaf builder (alpha + degree counts) MERGED with B' prep ------------
// blocks [0, SHEAF_BLKS): sheaf; blocks [SHEAF_BLKS, SHEAF_BLKS+PREPB_BLKS): prep_B.
__global__ void sheaf_prepB_kernel(const int* __restrict__ ni, const int* __restrict__ ei,
                                   const float* __restrict__ lng, const float* __restrict__ lnb,
                                   const float* __restrict__ sw,  const float* __restrict__ sb,
                                   const float* __restrict__ W2)
{
    if (blockIdx.x >= SHEAF_BLKS) {
        // ---- prep_B body: packed [hi(54) | hi(54) | lo(54)], B[n][k] = W2[k][n]
        int idx = (blockIdx.x - SHEAF_BLKS) * 256 + threadIdx.x;
        if (idx >= B_ROWS_PAD * KTOT) return;
        int n = idx / KTOT, k = idx - n * KTOT;
        __nv_bfloat16 o = __float2bfloat16(0.f);
        if (n < OUTD && k < KPACK) {
            int region = (k < PROJ) ? 0 : (k < 2 * PROJ) ? 1 : 2;
            int j = k - region * PROJ;
            float a = W2[(size_t)j * OUTD + n];
            __nv_bfloat16 h = __float2bfloat16(a);
            if (region == 2) o = __float2bfloat16(a - __bfloat162float(h));
            else             o = h;
        }
        g_Bbf[idx] = o;
        return;
    }

    __shared__ float s_sw[2 * HID * DH];
    __shared__ float s_sb[DH];
    __shared__ float s_g[2 * HID], s_b[2 * HID];
    int t = threadIdx.x;
    if (t < 2 * HID * DH) s_sw[t] = sw[t];
    if (t < DH) s_sb[t] = sb[t];
    if (t < 2 * HID) { s_g[t] = lng[t]; s_b[t] = lnb[t]; }
    __syncthreads();

    int k = blockIdx.x * blockDim.x + threadIdx.x;
    if (k >= NNZV) return;
    int n = ni[k], e = ei[k];

    float v[2 * HID];
    {
        const float4 a0 = *(const float4*)(g_xm + (size_t)n * ROW12);
        const float4 a1 = *(const float4*)(g_xm + (size_t)n * ROW12 + 4);
        v[0]=a0.x; v[1]=a0.y; v[2]=a0.z; v[3]=a0.w;
        v[4]=a1.x; v[5]=a1.y; v[6]=a1.z; v[7]=a1.w;
        v[8] = g_xm[(size_t)n * ROW12 + 8];
        const float4 b0 = *(const float4*)(g_em + (size_t)e * ROW12);
        const float4 b1 = *(const float4*)(g_em + (size_t)e * ROW12 + 4);
        v[9]=b0.x; v[10]=b0.y; v[11]=b0.z; v[12]=b0.w;
        v[13]=b1.x; v[14]=b1.y; v[15]=b1.z; v[16]=b1.w;
        v[17] = g_em[(size_t)e * ROW12 + 8];
    }
    float mean = 0.f;
    #pragma unroll
    for (int i = 0; i < 18; i++) mean += v[i];
    mean *= (1.0f / 18.0f);
    float var = 0.f;
    #pragma unroll
    for (int i = 0; i < 18; i++) { float d = v[i] - mean; var += d * d; }
    var *= (1.0f / 18.0f);
    float rs = rsqrtf(var + 1e-5f);
    float y[18];
    #pragma unroll
    for (int i = 0; i < 18; i++) y[i] = (v[i] - mean) * rs * s_g[i] + s_b[i];

    #pragma unroll
    for (int j = 0; j < DH; j++) {
        float z = s_sb[j];
        #pragma unroll
        for (int i = 0; i < 18; i++) z += y[i] * s_sw[i * DH + j];
        float h = 1.0f / (1.0f + __expf(-z));
        g_hsheaf[(size_t)k * DH + j] = h;
    }
    atomicAdd(&g_cnt_node[n], 1);
    atomicAdd(&g_cnt_edge[e], 1);
}

// ---------------- hierarchical scan (3 stages) ----------------
__global__ void scan1_kernel()
{
    __shared__ int wsum[32];
    const int* cnt = (blockIdx.y == 0) ? g_cnt_edge : g_cnt_node;
    int* off       = (blockIdx.y == 0) ? g_eoff : g_noff;
    int* bsum      = (blockIdx.y == 0) ? g_bsum_e : g_bsum_n;
    int len        = (blockIdx.y == 0) ? EE : NN;
    int nblk       = (len + 1023) >> 10;
    if (blockIdx.x >= nblk) return;

    int t = threadIdx.x, lane = t & 31, w = t >> 5;
    int i = blockIdx.x * 1024 + t;
    int v = (i < len) ? cnt[i] : 0;

    int sv = v;
    #pragma unroll
    for (int d = 1; d < 32; d <<= 1) {
        int u = __shfl_up_sync(0xFFFFFFFF, sv, d);
        if (lane >= d) sv += u;
    }
    if (lane == 31) wsum[w] = sv;
    __syncthreads();
    if (w == 0) {
        int ws = wsum[lane];
        #pragma unroll
        for (int d = 1; d < 32; d <<= 1) {
            int u = __shfl_up_sync(0xFFFFFFFF, ws, d);
            if (lane >= d) ws += u;
        }
        wsum[lane] = ws;
    }
    __syncthreads();
    int wbase = (w > 0) ? wsum[w - 1] : 0;
    if (i < len) off[i] = wbase + sv - v;
    if (t == 1023) bsum[blockIdx.x] = wbase + sv;
}

__global__ void scan2_kernel()
{
    int lane = threadIdx.x & 31;
    int nb_e = (EE + 1023) >> 10, nb_n = (NN + 1023) >> 10;
    int* bsum = (threadIdx.x < 32) ? g_bsum_e : g_bsum_n;
    int nb    = (threadIdx.x < 32) ? nb_e : nb_n;
    int v = (lane < nb) ? bsum[lane] : 0;
    int sv = v;
    #pragma unroll
    for (int d = 1; d < 32; d <<= 1) {
        int u = __shfl_up_sync(0xFFFFFFFF, sv, d);
        if (lane >= d) sv += u;
    }
    if (lane < nb) bsum[lane] = sv - v;
    if (lane == 31) {
        if (threadIdx.x < 32) g_eoff[EE] = sv;
        else                  g_noff[NN] = sv;
    }
}

__global__ void scan3_kernel()
{
    int* off        = (blockIdx.y == 0) ? g_eoff : g_noff;
    const int* bsum = (blockIdx.y == 0) ? g_bsum_e : g_bsum_n;
    int len         = (blockIdx.y == 0) ? EE : NN;
    int i = blockIdx.x * 1024 + threadIdx.x;
    if (i < len) off[i] += bsum[blockIdx.x];
}

// ---------------- CSR fill ----------------
__global__ void fill_kernel(const int* __restrict__ ni, const int* __restrict__ ei)
{
    int k = blockIdx.x * blockDim.x + threadIdx.x;
    if (k >= NNZV) return;
    int n = ni[k], e = ei[k];
    int pe = atomicAdd(&g_ecur[e], 1);
    g_elist[g_eoff[e] + pe] = make_int2(k, n);
    int pn = atomicAdd(&g_ncur[n], 1);
    g_nlist[g_noff[n] + pn] = make_int2(k, e);
}

// ---------------- per-layer h0 (layers >= 1): h0 = LN(x) @ conv_w[l] + conv_b[l] -------
__global__ void h0_kernel(const float* __restrict__ lng, const float* __restrict__ lnb,
                          const float* __restrict__ W,   const float* __restrict__ cb,
                          int l)
{
    __shared__ float sW[HID * HID];
    __shared__ float sg[HID], sb2[HID], scb[HID];
    int t = threadIdx.x;
    if (t < HID * HID) sW[t] = W[l * HID * HID + t];
    if (t < HID) { sg[t] = lng[l * HID + t]; sb2[t] = lnb[l * HID + t]; scb[t] = cb[l * HID + t]; }
    __syncthreads();

    int r = blockIdx.x * blockDim.x + threadIdx.x;
    if (r >= NN * DH) return;

    float v[HID];
    #pragma unroll
    for (int h = 0; h < HID; h++) v[h] = g_xproj[(size_t)r * HID + h];
    float mean = 0.f;
    #pragma unroll
    for (int h = 0; h < HID; h++) mean += v[h];
    mean *= (1.0f / HID);
    float var = 0.f;
    #pragma unroll
    for (int h = 0; h < HID; h++) { float d = v[h] - mean; var += d * d; }
    var *= (1.0f / HID);
    float rs = rsqrtf(var + 1e-5f);
    float y[HID];
    #pragma unroll
    for (int h = 0; h < HID; h++) y[h] = (v[h] - mean) * rs * sg[h] + sb2[h];

    #pragma unroll
    for (int c = 0; c < HID; c++) {
        float acc = scb[c];
        #pragma unroll
        for (int h = 0; h < HID; h++) acc += y[h] * sW[h * HID + c];
        g_h0[(size_t)r * ROW12 + c] = acc;
    }
}

// ---------------- warp-per-edge gather ----------------
__global__ void edge_gather_kernel()
{
    int w = (blockIdx.x * blockDim.x + threadIdx.x) >> 5;
    int lane = threadIdx.x & 31;
    if (w >= EE) return;
    int s = g_eoff[w], t = g_eoff[w + 1];
    float be = (t > s) ? (1.0f / (float)(t - s)) : 0.f;
    int j = lane % DH, q = lane / DH;
    bool act = (lane < 30);

    float a[HID];
    #pragma unroll
    for (int h = 0; h < HID; h++) a[h] = 0.f;

    if (act) {
        for (int p = s + q; p < t; p += 5) {
            int2 kn = g_elist[p];
            float al = g_hsheaf[(size_t)kn.x * DH + j];
            const float* src = g_h0 + ((size_t)kn.y * DH + j) * ROW12;
            float4 v0 = *(const float4*)src;
            float4 v1 = *(const float4*)(src + 4);
            float  v2 = src[8];
            a[0] += al * v0.x; a[1] += al * v0.y; a[2] += al * v0.z; a[3] += al * v0.w;
            a[4] += al * v1.x; a[5] += al * v1.y; a[6] += al * v1.z; a[7] += al * v1.w;
            a[8] += al * v2;
        }
    }
    #pragma unroll
    for (int h = 0; h < HID; h++) {
        float v = a[h];
        float v6  = __shfl_down_sync(0xFFFFFFFF, v, 6);
        float v12 = __shfl_down_sync(0xFFFFFFFF, v, 12);
        float v18 = __shfl_down_sync(0xFFFFFFFF, v, 18);
        float v24 = __shfl_down_sync(0xFFFFFFFF, v, 24);
        a[h] = v + v6 + v12 + v18 + v24;
    }
    if (lane < DH) {
        float* dst = g_m + ((size_t)w * DH + j) * ROW12;
        *(float4*)dst       = make_float4(a[0] * be, a[1] * be, a[2] * be, a[3] * be);
        *(float4*)(dst + 4) = make_float4(a[4] * be, a[5] * be, a[6] * be, a[7] * be);
        dst[8] = a[8] * be;
    }
}

// ---------------- warp-per-node gather + finalize (+ packed bf16 A emit last layer) ----
__global__ void node_gather_fin_kernel(const float* __restrict__ cbias, int l)
{
    int w = (blockIdx.x * blockDim.x + threadIdx.x) >> 5;
    int lane = threadIdx.x & 31;
    if (w >= NN) return;
    int s = g_noff[w], t = g_noff[w + 1];
    float dv = (t > s) ? (1.0f / (float)(t - s)) : 0.f;
    int j = lane % DH, q = lane / DH;
    bool act = (lane < 30);

    float a[HID];
    #pragma unroll
    for (int h = 0; h < HID; h++) a[h] = 0.f;

    if (act) {
        for (int p = s + q; p < t; p += 5) {
            int2 ke = g_nlist[p];
            float al = g_hsheaf[(size_t)ke.x * DH + j];
            const float* src = g_m + ((size_t)ke.y * DH + j) * ROW12;
            float4 v0 = *(const float4*)src;
            float4 v1 = *(const float4*)(src + 4);
            float  v2 = src[8];
            a[0] += al * v0.x; a[1] += al * v0.y; a[2] += al * v0.z; a[3] += al * v0.w;
            a[4] += al * v1.x; a[5] += al * v1.y; a[6] += al * v1.z; a[7] += al * v1.w;
            a[8] += al * v2;
        }
    }
    #pragma unroll
    for (int h = 0; h < HID; h++) {
        float v = a[h];
        float v6  = __shfl_down_sync(0xFFFFFFFF, v, 6);
        float v12 = __shfl_down_sync(0xFFFFFFFF, v, 12);
        float v18 = __shfl_down_sync(0xFFFFFFFF, v, 18);
        float v24 = __shfl_down_sync(0xFFFFFFFF, v, 24);
        a[h] = v + v6 + v12 + v18 + v24;
    }

    if (lane < DH) {
        size_t idx = (size_t)w * DH + j;
        const float* h0r = g_h0 + idx * ROW12;
        float o[HID];
        #pragma unroll
        for (int h = 0; h < HID; h++)
            o[h] = a[h] * dv + h0r[h] + cbias[l * HID + h];

        if (l == 0) {
            #pragma unroll
            for (int h = 0; h < HID; h++) {
                float v = o[h];
                v = (v > 0.f) ? v : expm1f(v);   // ELU
                g_xproj[idx * HID + h] = v;
            }
        } else {
            // packed A' row: [hi(54) | lo(54) | hi(54)], this thread owns cols j*9..j*9+8
            __nv_bfloat16* arow = g_Abf + (size_t)w * KTOT + j * HID;
            #pragma unroll
            for (int h = 0; h < HID; h++) {
                float v = o[h];
                __nv_bfloat16 hi = __float2bfloat16(v);
                __nv_bfloat16 lo = __float2bfloat16(v - __bfloat162float(hi));
                arow[h]            = hi;
                arow[PROJ + h]     = lo;
                arow[2 * PROJ + h] = hi;
            }
        }
    }
}

// ---------------- HMMA lin2 GEMM v5: 128x256 tile, packed K=176, 2-stage chunk pipe ----
#define GTM 128
#define GTN 256
#define CST 72                              // chunk smem bf16 stride
#define STAGE_A (GTM * CST)                 // 9216 bf16
#define STAGE_ELEMS ((GTM + GTN) * CST)     // 27648 bf16 = 55296 B
#define GEMM_SMEM_BYTES (2 * STAGE_ELEMS * 2)   // 110592 B

#define LDSM_X4(r, addr) \
    asm volatile("ldmatrix.sync.aligned.m8n8.x4.shared.b16 {%0,%1,%2,%3}, [%4];" \
        : "=r"((r)[0]), "=r"((r)[1]), "=r"((r)[2]), "=r"((r)[3]) : "r"(addr))
#define MMA16816(d, a, b0, b1) \
    asm volatile("mma.sync.aligned.m16n8k16.row.col.f32.bf16.bf16.f32 " \
        "{%0,%1,%2,%3}, {%4,%5,%6,%7}, {%8,%9}, {%0,%1,%2,%3};" \
        : "+f"((d)[0]), "+f"((d)[1]), "+f"((d)[2]), "+f"((d)[3]) \
        : "r"((a)[0]), "r"((a)[1]), "r"((a)[2]), "r"((a)[3]), "r"(b0), "r"(b1))

__device__ __forceinline__ uint32_t smem_u32(const void* p) {
    uint32_t a;
    asm("{ .reg .u64 t; cvta.to.shared.u64 t, %1; cvt.u32.u64 %0, t; }" : "=r"(a) : "l"(p));
    return a;
}
__device__ __forceinline__ void cp16(uint32_t dst, const void* src) {
    asm volatile("cp.async.cg.shared.global [%0], [%1], 16;" :: "r"(dst), "l"(src));
}

__global__ void __launch_bounds__(512, 1)
lin2_mma_kernel(const float* __restrict__ bias, float* __restrict__ C)
{
    extern __shared__ __nv_bfloat16 smem[];
    __shared__ float sbias[GTN];

    int tid = threadIdx.x, lane = tid & 31, wid = tid >> 5;
    int wm = wid >> 2, wn = wid & 3;            // warp grid 4(M) x 4(N)
    int n0 = blockIdx.x * GTN, m0 = blockIdx.y * GTM;
    uint32_t smb = smem_u32(smem);

    // async load of chunk c (cols c*64..) into stage st; chunks are 64/64/48 cols
    auto load_chunk = [&](int c, int st) {
        int col = c * 64, nseg = (c == 2) ? 6 : 8;
        uint32_t base = smb + (uint32_t)(st * STAGE_ELEMS) * 2;
        for (int i = tid; i < GTM * nseg; i += 512) {
            int r = i / nseg, s = i - r * nseg;
            cp16(base + (uint32_t)(r * CST + s * 8) * 2,
                 g_Abf + (size_t)(m0 + r) * KTOT + col + s * 8);
        }
        uint32_t bb = base + (uint32_t)STAGE_A * 2;
        for (int i = tid; i < GTN * nseg; i += 512) {
            int r = i / nseg, s = i - r * nseg;
            cp16(bb + (uint32_t)(r * CST + s * 8) * 2,
                 g_Bbf + (size_t)(n0 + r) * KTOT + col + s * 8);
        }
        asm volatile("cp.async.commit_group;" ::: "memory");
    };

    load_chunk(0, 0);

    for (int i = tid; i < GTN; i += 512) {
        int n = n0 + i;
        sbias[i] = (n < OUTD) ? bias[n] : 0.f;
    }

    float acc[2][8][4];
    #pragma unroll
    for (int mt = 0; mt < 2; mt++)
        #pragma unroll
        for (int nt = 0; nt < 8; nt++)
            #pragma unroll
            for (int q = 0; q < 4; q++) acc[mt][nt][q] = 0.f;

    for (int c = 0; c < 3; c++) {
        if (c < 2) {
            load_chunk(c + 1, (c + 1) & 1);
            asm volatile("cp.async.wait_group 1;" ::: "memory");
        } else {
            asm volatile("cp.async.wait_group 0;" ::: "memory");
        }
        __syncthreads();

        uint32_t a_base = smb + (uint32_t)((c & 1) * STAGE_ELEMS) * 2;
        uint32_t b_base = a_base + (uint32_t)STAGE_A * 2;
        int nks = (c == 2) ? 3 : 4;

        #pragma unroll 4
        for (int ks = 0; ks < nks; ks++) {
            uint32_t af[2][4], bf[4][4];
            #pragma unroll
            for (int mt = 0; mt < 2; mt++) {
                int row = wm * 32 + mt * 16 + (lane & 15);
                int col = ks * 16 + (lane >> 4) * 8;
                LDSM_X4(af[mt], a_base + (uint32_t)(row * CST + col) * 2);
            }
            #pragma unroll
            for (int p = 0; p < 4; p++) {
                int q = lane >> 3, rl = lane & 7;
                int nrow = wn * 64 + p * 16 + (q >> 1) * 8 + rl;
                int col = ks * 16 + (q & 1) * 8;
                LDSM_X4(bf[p], b_base + (uint32_t)(nrow * CST + col) * 2);
            }
            #pragma unroll
            for (int mt = 0; mt < 2; mt++)
                #pragma unroll
                for (int nt = 0; nt < 8; nt++)
                    MMA16816(acc[mt][nt], af[mt],
                             bf[nt >> 1][(nt & 1) * 2], bf[nt >> 1][(nt & 1) * 2 + 1]);
        }
        __syncthreads();
    }

    // epilogue
    int gid = lane >> 2, tig = lane & 3;
    #pragma unroll
    for (int mt = 0; mt < 2; mt++) {
        int r0 = m0 + wm * 32 + mt * 16 + gid;
        int r1 = r0 + 8;
        #pragma unroll
        for (int nt = 0; nt < 8; nt++) {
            int lc = wn * 64 + nt * 8 + tig * 2;
            int c  = n0 + lc;
            if (c < OUTD) {
                float b0 = sbias[lc], b1 = sbias[lc + 1];
                if (r0 < NN) {
                    float2 v = make_float2(acc[mt][nt][0] + b0, acc[mt][nt][1] + b1);
                    *(float2*)(C + (size_t)r0 * OUTD + c) = v;
                }
                if (r1 < NN) {
                    float2 v = make_float2(acc[mt][nt][2] + b0, acc[mt][nt][3] + b1);
                    *(float2*)(C + (size_t)r1 * OUTD + c) = v;
                }
            }
        }
    }
}

// ---------------- launch ----------------
extern "C" void kernel_launch(void* const* d_in, const int* in_sizes, int n_in,
                              void* d_out, int out_size)
{
    const float* x        = (const float*)d_in[0];
    const float* hedge    = (const float*)d_in[1];
    const int*   node_idx = (const int*)  d_in[2];
    const int*   edge_idx = (const int*)  d_in[3];
    const float* lin_w    = (const float*)d_in[4];
    const float* lin_b    = (const float*)d_in[5];
    const float* s_ln_g   = (const float*)d_in[6];
    const float* s_ln_b   = (const float*)d_in[7];
    const float* sheaf_w  = (const float*)d_in[8];
    const float* sheaf_b  = (const float*)d_in[9];
    const float* c_ln_g   = (const float*)d_in[10];
    const float* c_ln_b   = (const float*)d_in[11];
    const float* conv_w   = (const float*)d_in[12];
    const float* conv_b   = (const float*)d_in[13];
    const float* conv_bias= (const float*)d_in[14];
    const float* lin2_w   = (const float*)d_in[15];
    const float* lin2_b   = (const float*)d_in[16];
    float* out = (float*)d_out;

    cudaFuncSetAttribute(lin2_mma_kernel,
                         cudaFuncAttributeMaxDynamicSharedMemorySize,
                         GEMM_SMEM_BYTES);

    // proj + fused layer-0 h0 + count zeroing (8 rows/block, R12 config)
    proj_kernel<<<(NN + EE + 7) / 8, 64>>>(x, hedge, lin_w, lin_b,
                                           c_ln_g, c_ln_b, conv_w, conv_b);
    // sheaf + merged B' prep
    sheaf_prepB_kernel<<<SHEAF_BLKS + PREPB_BLKS, 256>>>(node_idx, edge_idx,
                                                         s_ln_g, s_ln_b,
                                                         sheaf_w, sheaf_b, lin2_w);
    {
        dim3 g1((NN + 1023) / 1024, 2);
        scan1_kernel<<<g1, 1024>>>();
        scan2_kernel<<<1, 64>>>();
        scan3_kernel<<<g1, 1024>>>();
    }
    fill_kernel<<<(NNZV + 255) / 256, 256>>>(node_idx, edge_idx);

    for (int l = 0; l < NLAY; l++) {
        if (l > 0)
            h0_kernel<<<(NN * DH + 255) / 256, 256>>>(c_ln_g, c_ln_b, conv_w, conv_b, l);
        edge_gather_kernel<<<(EE * 32 + 255) / 256, 256>>>();
        node_gather_fin_kernel<<<(NN * 32 + 255) / 256, 256>>>(conv_bias, l);
    }

    dim3 grid((OUTD + GTN - 1) / GTN, (NN + GTM - 1) / GTM);   // 20 x 157
    lin2_mma_kernel<<<grid, 512, GEMM_SMEM_BYTES>>>(lin2_b, out);
}